// round 3
// baseline (speedup 1.0000x reference)
#include <cuda_runtime.h>
#include <cstdint>
#include <cstdio>

// Problem constants
#define BATCH   32
#define HID     1024
#define NGATE   4096          // 4*HID
#define TSTEPS  511           // T-1
#define MTOT    16352         // TSTEPS*BATCH
#define RES_ELEMS (511*32*1024)

// ---------------- device scratch (no runtime allocation allowed) -------------
__device__ float    g_xp[(size_t)MTOT * NGATE];   // precomputed x-projection (+bias), fp32, ~268MB
__device__ float    g_h[2][BATCH * HID];          // double-buffered hidden state
__device__ unsigned g_bar;                        // grid barrier counter (monotonic per launch)

// ---------------- small helpers ----------------------------------------------
__device__ __forceinline__ unsigned f2tf(float f) {
    unsigned u;
    asm("cvt.rna.tf32.f32 %0, %1;" : "=r"(u) : "f"(f));
    return u;
}
__device__ __forceinline__ float ldcg(const float* p) {
    float v;
    asm volatile("ld.global.cg.f32 %0, [%1];" : "=f"(v) : "l"(p));
    return v;
}
__device__ __forceinline__ void mma8(float c[4], unsigned a0, unsigned a1, unsigned a2,
                                     unsigned a3, unsigned b0, unsigned b1) {
    asm volatile(
        "mma.sync.aligned.m16n8k8.row.col.f32.tf32.tf32.f32 "
        "{%0,%1,%2,%3}, {%4,%5,%6,%7}, {%8,%9}, {%0,%1,%2,%3};"
        : "+f"(c[0]), "+f"(c[1]), "+f"(c[2]), "+f"(c[3])
        : "r"(a0), "r"(a1), "r"(a2), "r"(a3), "r"(b0), "r"(b1));
}
__device__ __forceinline__ float sigf(float x) { return 1.f / (1.f + __expf(-x)); }

// ---------------- init: reset barrier, load h0 into buffer 0 -----------------
__global__ void init_kernel(const float* __restrict__ h0) {
    int i = blockIdx.x * blockDim.x + threadIdx.x;
    if (i == 0) g_bar = 0u;
    if (i < BATCH * HID) g_h[0][i] = h0[i];
}

// ---------------- x_proj: xp[t*32+b][g] = emb[tgt[b][t]] . W_ih[g] + bias ----
// Tiled tf32 mma GEMM. BM=128, BN=128, BK=32, 256 threads, warp grid 2(m)x4(n).
__global__ void __launch_bounds__(256)
xproj_kernel(const int* __restrict__ tgt, const float* __restrict__ emb,
             const float* __restrict__ W, const float* __restrict__ b_ih,
             const float* __restrict__ b_hh)
{
    __shared__ unsigned As[128][32];   // A tile, rotated layout: phys col4 = (c4 + (m&7)) & 7
    __shared__ unsigned Bs[128][32];   // B tile (W_ih rows), same rotation

    const int nb = blockIdx.x, mb = blockIdx.y;
    const int tid = threadIdx.x, lane = tid & 31, wid = tid >> 5;
    const int warp_m = wid & 1, warp_n = wid >> 1;
    const int c4 = tid & 7, row0 = tid >> 3;   // each thread loads 4 rows x one float4
    const int g = lane >> 2, tg = lane & 3;

    // tokens for this thread's 4 A rows (fixed over the k loop)
    int toks[4];
#pragma unroll
    for (int r = 0; r < 4; ++r) {
        int m  = row0 + r * 32;
        int mg = mb * 128 + m;              // global m = t*32 + b ; mg<=16383 -> t<=511 in-range
        int bb = mg & 31, tt = mg >> 5;
        int tok = tgt[bb * 512 + tt];
        toks[r] = (tok < 0 || tok > 31999) ? 0 : tok;
    }

    float acc[4][4][4];
#pragma unroll
    for (int mt = 0; mt < 4; ++mt)
#pragma unroll
        for (int nt = 0; nt < 4; ++nt)
#pragma unroll
            for (int i = 0; i < 4; ++i) acc[mt][nt][i] = 0.f;

    for (int kt = 0; kt < 32; ++kt) {
        const int koff = kt * 32 + c4 * 4;
#pragma unroll
        for (int r = 0; r < 4; ++r) {
            int m = row0 + r * 32;
            float4 va = *(const float4*)(emb + (size_t)toks[r] * 1024 + koff);
            unsigned* da = &As[m][((c4 + m) & 7) * 4];
            da[0] = f2tf(va.x); da[1] = f2tf(va.y); da[2] = f2tf(va.z); da[3] = f2tf(va.w);
            float4 vb = *(const float4*)(W + (size_t)(nb * 128 + m) * 1024 + koff);
            unsigned* db = &Bs[m][((c4 + m) & 7) * 4];
            db[0] = f2tf(vb.x); db[1] = f2tf(vb.y); db[2] = f2tf(vb.z); db[3] = f2tf(vb.w);
        }
        __syncthreads();
#pragma unroll
        for (int ks = 0; ks < 4; ++ks) {
            const int kb = ks * 8;
            unsigned a[4][4], bf[4][2];
#pragma unroll
            for (int mt = 0; mt < 4; ++mt) {
                int m   = warp_m * 64 + mt * 16 + g;
                int rot = 4 * (m & 7);
                a[mt][0] = As[m    ][(kb + tg     + rot) & 31];
                a[mt][1] = As[m + 8][(kb + tg     + rot) & 31];
                a[mt][2] = As[m    ][(kb + tg + 4 + rot) & 31];
                a[mt][3] = As[m + 8][(kb + tg + 4 + rot) & 31];
            }
#pragma unroll
            for (int nt = 0; nt < 4; ++nt) {
                int n   = warp_n * 32 + nt * 8 + g;
                int rot = 4 * (n & 7);
                bf[nt][0] = Bs[n][(kb + tg     + rot) & 31];
                bf[nt][1] = Bs[n][(kb + tg + 4 + rot) & 31];
            }
#pragma unroll
            for (int mt = 0; mt < 4; ++mt)
#pragma unroll
                for (int nt = 0; nt < 4; ++nt)
                    mma8(acc[mt][nt], a[mt][0], a[mt][1], a[mt][2], a[mt][3],
                         bf[nt][0], bf[nt][1]);
        }
        __syncthreads();
    }

    // epilogue: add bias, write to g_xp, mask m tail (MTOT = 16352)
#pragma unroll
    for (int mt = 0; mt < 4; ++mt) {
#pragma unroll
        for (int nt = 0; nt < 4; ++nt) {
            int m0 = mb * 128 + warp_m * 64 + mt * 16 + g;
            int n0 = nb * 128 + warp_n * 32 + nt * 8 + tg * 2;
            float bia0 = b_ih[n0] + b_hh[n0];
            float bia1 = b_ih[n0 + 1] + b_hh[n0 + 1];
            if (m0 < MTOT) {
                g_xp[(size_t)m0 * NGATE + n0]     = acc[mt][nt][0] + bia0;
                g_xp[(size_t)m0 * NGATE + n0 + 1] = acc[mt][nt][1] + bia1;
            }
            if (m0 + 8 < MTOT) {
                g_xp[(size_t)(m0 + 8) * NGATE + n0]     = acc[mt][nt][2] + bia0;
                g_xp[(size_t)(m0 + 8) * NGATE + n0 + 1] = acc[mt][nt][3] + bia1;
            }
        }
    }
}

// ---------------- persistent recurrent kernel --------------------------------
// 128 CTAs x 256 threads. CTA c owns hidden units [c*8, c*8+8) (32 W_hh rows:
// gates i,f,g,o). W_hh fragments pre-packed (tf32) in SMEM; per step:
//   P[b][r] = h_t . W_row  via 8-way K-split tf32 mma, reduce in SMEM,
//   gate math per (b, jj) thread (c state lives in a register), grid barrier.
#define LSTM_SMEM (32768u * 4u + 8448u * 4u)   // Wfrag + reduction buffer

__global__ void __launch_bounds__(256)
lstm_kernel(const float* __restrict__ c0, const float* __restrict__ W_hh,
            float* __restrict__ out, int out_size)
{
    extern __shared__ unsigned sh[];
    unsigned* Wf  = sh;                    // 32768 u32: [warp][16 s][4 nt][32 lane][2]
    float*    red = (float*)(sh + 32768);  // 8448 f32: idx(m,n,w) = (m*33+n)*8+w

    const int tid = threadIdx.x, lane = tid & 31, wid = tid >> 5;
    const int g = lane >> 2, tg = lane & 3;
    const int j0 = blockIdx.x * 8;

    // pack this CTA's W_hh rows into mma B-fragment order (tf32)
#pragma unroll
    for (int s = 0; s < 16; ++s) {
#pragma unroll
        for (int nt = 0; nt < 4; ++nt) {
            int r  = nt * 8 + g;                    // local row 0..31
            int q  = r >> 3, jj = r & 7;
            size_t grow = (size_t)(q * 1024 + j0 + jj) * 1024;
            int k  = wid * 128 + s * 8 + tg;
            int idx = (((wid * 16 + s) * 4 + nt) * 32 + lane) * 2;
            Wf[idx]     = f2tf(W_hh[grow + k]);
            Wf[idx + 1] = f2tf(W_hh[grow + k + 4]);
        }
    }
    const int b = tid >> 3, jj = tid & 7;     // thread owns cell (batch b, unit j0+jj)
    float c_reg = c0[b * 1024 + j0 + jj];
    __syncthreads();

    for (int t = 0; t < TSTEPS; ++t) {
        const float* h = g_h[t & 1];

        // prefetch this thread's 4 gate pre-activations from g_xp
        float xpv[4];
        const float* xprow = &g_xp[(size_t)(t * 32 + b) * NGATE + j0 + jj];
#pragma unroll
        for (int q = 0; q < 4; ++q) xpv[q] = __ldg(xprow + q * 1024);

        // mma phase: warp wid handles K slice [wid*128, wid*128+128)
        float C[8][4];
#pragma unroll
        for (int i = 0; i < 8; ++i) { C[i][0] = 0.f; C[i][1] = 0.f; C[i][2] = 0.f; C[i][3] = 0.f; }

#pragma unroll 4
        for (int s = 0; s < 16; ++s) {
            int k = wid * 128 + s * 8 + tg;
            const float* hk = h + k;
            unsigned a0 = f2tf(ldcg(hk + (g     ) * 1024));
            unsigned a1 = f2tf(ldcg(hk + (g +  8) * 1024));
            unsigned a2 = f2tf(ldcg(hk + (g     ) * 1024 + 4));
            unsigned a3 = f2tf(ldcg(hk + (g +  8) * 1024 + 4));
            unsigned a4 = f2tf(ldcg(hk + (g + 16) * 1024));
            unsigned a5 = f2tf(ldcg(hk + (g + 24) * 1024));
            unsigned a6 = f2tf(ldcg(hk + (g + 16) * 1024 + 4));
            unsigned a7 = f2tf(ldcg(hk + (g + 24) * 1024 + 4));
            int idx0 = (((wid * 16 + s) * 4) * 32 + lane) * 2;
#pragma unroll
            for (int nt = 0; nt < 4; ++nt) {
                unsigned b0 = Wf[idx0 + nt * 64];
                unsigned b1 = Wf[idx0 + nt * 64 + 1];
                mma8(C[nt],     a0, a1, a2, a3, b0, b1);   // batches 0..15
                mma8(C[4 + nt], a4, a5, a6, a7, b0, b1);   // batches 16..31
            }
        }

        // write K-split partials to SMEM
#pragma unroll
        for (int mt = 0; mt < 2; ++mt) {
#pragma unroll
            for (int nt = 0; nt < 4; ++nt) {
                float* cc = C[mt * 4 + nt];
                int m  = mt * 16 + g;
                int n0 = nt * 8 + tg * 2;
                red[((m)     * 33 + n0    ) * 8 + wid] = cc[0];
                red[((m)     * 33 + n0 + 1) * 8 + wid] = cc[1];
                red[((m + 8) * 33 + n0    ) * 8 + wid] = cc[2];
                red[((m + 8) * 33 + n0 + 1) * 8 + wid] = cc[3];
            }
        }
        __syncthreads();

        // gate math: one thread per (b, jj)
        float z[4];
#pragma unroll
        for (int q = 0; q < 4; ++q) {
            int r = q * 8 + jj;
            const float4* p = (const float4*)&red[(b * 33 + r) * 8];
            float4 s0 = p[0], s1 = p[1];
            z[q] = xpv[q] + (((s0.x + s0.y) + (s0.z + s0.w)) +
                             ((s1.x + s1.y) + (s1.z + s1.w)));
        }
        float iv = sigf(z[0]);
        float fv = sigf(z[1]);
        float gv = tanhf(z[2]);
        float ov = sigf(z[3]);
        c_reg = fv * c_reg + iv * gv;
        float hv = ov * tanhf(c_reg);

        g_h[(t + 1) & 1][b * 1024 + j0 + jj] = hv;
        out[((size_t)b * TSTEPS + t) * 1024 + j0 + jj] = hv;   // res[b][t][j]
        if (t == TSTEPS - 1 && out_size >= RES_ELEMS + 2 * BATCH * HID) {
            out[RES_ELEMS + b * 1024 + j0 + jj]                 = hv;     // hT
            out[RES_ELEMS + BATCH * HID + b * 1024 + j0 + jj]   = c_reg;  // cT
        }

        if (t < TSTEPS - 1) {
            // grid barrier (monotonic counter; 128 co-resident CTAs)
            __syncthreads();
            if (tid == 0) {
                __threadfence();
                atomicAdd(&g_bar, 1u);
                unsigned target = 128u * (unsigned)(t + 1);
                unsigned v;
                for (;;) {
                    asm volatile("ld.acquire.gpu.global.u32 %0, [%1];"
                                 : "=r"(v) : "l"(&g_bar));
                    if (v >= target) break;
                    __nanosleep(40);
                }
            }
            __syncthreads();
        }
    }
}

// ---------------- launch ------------------------------------------------------
extern "C" void kernel_launch(void* const* d_in, const int* in_sizes, int n_in,
                              void* d_out, int out_size)
{
    const int*   tgt  = (const int*)  d_in[0];
    const float* h0   = (const float*)d_in[1];
    const float* c0   = (const float*)d_in[2];
    // d_in[3] encoder_outputs, d_in[4] src_lengths: unused by the reference
    const float* emb  = (const float*)d_in[5];
    const float* W_ih = (const float*)d_in[6];
    const float* W_hh = (const float*)d_in[7];
    const float* b_ih = (const float*)d_in[8];
    const float* b_hh = (const float*)d_in[9];
    float* out = (float*)d_out;

    cudaFuncSetAttribute(lstm_kernel, cudaFuncAttributeMaxDynamicSharedMemorySize,
                         (int)LSTM_SMEM);

    init_kernel<<<128, 256>>>(h0);

    dim3 grid_x(32, 128);                 // (n blocks, m blocks)
    xproj_kernel<<<grid_x, 256>>>(tgt, emb, W_ih, b_ih, b_hh);

    lstm_kernel<<<128, 256, LSTM_SMEM>>>(c0, W_hh, out, out_size);
}

// round 4
// speedup vs baseline: 1.7387x; 1.7387x over previous
#include <cuda_runtime.h>
#include <cstdint>

// Problem constants
#define BATCH   32
#define HID     1024
#define NGATE   4096          // 4*HID
#define TSTEPS  511           // T-1
#define MTOT    16352         // TSTEPS*BATCH
#define RES_ELEMS (511*32*1024)

// ---------------- device scratch (no runtime allocation allowed) -------------
__device__ float    g_xp[(size_t)MTOT * NGATE];    // x-projection (+bias), fp32
__device__ unsigned g_hp[2][128 * 32 * 8];         // h double-buffered, tf32 mma-fragment packed
__device__ unsigned g_count;                        // barrier arrivals (self-resetting)
__device__ unsigned g_epoch;                        // barrier epoch (monotonic across replays)

// ---------------- small helpers ----------------------------------------------
__device__ __forceinline__ unsigned f2tf(float f) {
    unsigned u;
    asm("cvt.rna.tf32.f32 %0, %1;" : "=r"(u) : "f"(f));
    return u;
}
__device__ __forceinline__ uint4 ldcg4(const unsigned* p) {
    uint4 v;
    asm volatile("ld.global.cg.v4.u32 {%0,%1,%2,%3}, [%4];"
                 : "=r"(v.x), "=r"(v.y), "=r"(v.z), "=r"(v.w) : "l"(p));
    return v;
}
__device__ __forceinline__ void mma8(float c[4], unsigned a0, unsigned a1, unsigned a2,
                                     unsigned a3, unsigned b0, unsigned b1) {
    asm volatile(
        "mma.sync.aligned.m16n8k8.row.col.f32.tf32.tf32.f32 "
        "{%0,%1,%2,%3}, {%4,%5,%6,%7}, {%8,%9}, {%0,%1,%2,%3};"
        : "+f"(c[0]), "+f"(c[1]), "+f"(c[2]), "+f"(c[3])
        : "r"(a0), "r"(a1), "r"(a2), "r"(a3), "r"(b0), "r"(b1));
}
__device__ __forceinline__ float fsig(float x) {
    return __fdividef(1.f, 1.f + __expf(-x));
}
__device__ __forceinline__ float ftanh(float x) {
    return __fmaf_rn(2.f, fsig(2.f * x), -1.f);
}
// fragment-pack slot for h element (b, j)
__device__ __forceinline__ int hp_index(int b, int j) {
    int kb   = j >> 3;
    int ln   = (b & 7) * 4 + (j & 3);
    int q    = b >> 3;
    int d    = (j >> 2) & 1;
    int slot = ((q >> 1) << 2) | (d << 1) | (q & 1);
    return (kb * 32 + ln) * 8 + slot;
}

// ---------------- grid barrier (epoch-based, replay-safe, no reset kernel) ---
__device__ __forceinline__ void grid_bar(int tid) {
    __syncthreads();
    if (tid == 0) {
        unsigned e;
        asm volatile("ld.acquire.gpu.global.u32 %0, [%1];" : "=r"(e) : "l"(&g_epoch));
        unsigned old;
        asm volatile("atom.acq_rel.gpu.global.add.u32 %0, [%1], %2;"
                     : "=r"(old) : "l"(&g_count), "r"(1u));
        if (old == 127u) {
            asm volatile("st.relaxed.gpu.global.u32 [%0], %1;" :: "l"(&g_count), "r"(0u));
            unsigned dummy;
            asm volatile("atom.release.gpu.global.add.u32 %0, [%1], %2;"
                         : "=r"(dummy) : "l"(&g_epoch), "r"(1u));
        } else {
            unsigned v;
            do {
                asm volatile("ld.acquire.gpu.global.u32 %0, [%1];" : "=r"(v) : "l"(&g_epoch));
            } while (v == e);
        }
    }
    __syncthreads();
}

// ---------------- x_proj: xp[t*32+b][g] = emb[tgt[b][t]] . W_ih[g] + bias ----
__global__ void __launch_bounds__(256)
xproj_kernel(const int* __restrict__ tgt, const float* __restrict__ emb,
             const float* __restrict__ W, const float* __restrict__ b_ih,
             const float* __restrict__ b_hh)
{
    __shared__ unsigned As[128][32];   // rotated: phys col4 = (c4 + (m&7)) & 7
    __shared__ unsigned Bs[128][32];

    const int nb = blockIdx.x, mb = blockIdx.y;
    const int tid = threadIdx.x, lane = tid & 31, wid = tid >> 5;
    const int warp_m = wid & 1, warp_n = wid >> 1;
    const int c4 = tid & 7, row0 = tid >> 3;
    const int g = lane >> 2, tg = lane & 3;

    int toks[4];
#pragma unroll
    for (int r = 0; r < 4; ++r) {
        int m  = row0 + r * 32;
        int mg = mb * 128 + m;
        int bb = mg & 31, tt = mg >> 5;
        int tok = tgt[bb * 512 + tt];
        toks[r] = (tok < 0 || tok > 31999) ? 0 : tok;
    }

    float acc[4][4][4];
#pragma unroll
    for (int mt = 0; mt < 4; ++mt)
#pragma unroll
        for (int nt = 0; nt < 4; ++nt)
#pragma unroll
            for (int i = 0; i < 4; ++i) acc[mt][nt][i] = 0.f;

    for (int kt = 0; kt < 32; ++kt) {
        const int koff = kt * 32 + c4 * 4;
#pragma unroll
        for (int r = 0; r < 4; ++r) {
            int m = row0 + r * 32;
            float4 va = *(const float4*)(emb + (size_t)toks[r] * 1024 + koff);
            unsigned* da = &As[m][((c4 + m) & 7) * 4];
            da[0] = f2tf(va.x); da[1] = f2tf(va.y); da[2] = f2tf(va.z); da[3] = f2tf(va.w);
            float4 vb = *(const float4*)(W + (size_t)(nb * 128 + m) * 1024 + koff);
            unsigned* db = &Bs[m][((c4 + m) & 7) * 4];
            db[0] = f2tf(vb.x); db[1] = f2tf(vb.y); db[2] = f2tf(vb.z); db[3] = f2tf(vb.w);
        }
        __syncthreads();
#pragma unroll
        for (int ks = 0; ks < 4; ++ks) {
            const int kb = ks * 8;
            unsigned a[4][4], bf[4][2];
#pragma unroll
            for (int mt = 0; mt < 4; ++mt) {
                int m   = warp_m * 64 + mt * 16 + g;
                int rot = 4 * (m & 7);
                a[mt][0] = As[m    ][(kb + tg     + rot) & 31];
                a[mt][1] = As[m + 8][(kb + tg     + rot) & 31];
                a[mt][2] = As[m    ][(kb + tg + 4 + rot) & 31];
                a[mt][3] = As[m + 8][(kb + tg + 4 + rot) & 31];
            }
#pragma unroll
            for (int nt = 0; nt < 4; ++nt) {
                int n   = warp_n * 32 + nt * 8 + g;
                int rot = 4 * (n & 7);
                bf[nt][0] = Bs[n][(kb + tg     + rot) & 31];
                bf[nt][1] = Bs[n][(kb + tg + 4 + rot) & 31];
            }
#pragma unroll
            for (int mt = 0; mt < 4; ++mt)
#pragma unroll
                for (int nt = 0; nt < 4; ++nt)
                    mma8(acc[mt][nt], a[mt][0], a[mt][1], a[mt][2], a[mt][3],
                         bf[nt][0], bf[nt][1]);
        }
        __syncthreads();
    }

#pragma unroll
    for (int mt = 0; mt < 4; ++mt) {
#pragma unroll
        for (int nt = 0; nt < 4; ++nt) {
            int m0 = mb * 128 + warp_m * 64 + mt * 16 + g;
            int n0 = nb * 128 + warp_n * 32 + nt * 8 + tg * 2;
            float bia0 = b_ih[n0] + b_hh[n0];
            float bia1 = b_ih[n0 + 1] + b_hh[n0 + 1];
            if (m0 < MTOT) {
                g_xp[(size_t)m0 * NGATE + n0]     = acc[mt][nt][0] + bia0;
                g_xp[(size_t)m0 * NGATE + n0 + 1] = acc[mt][nt][1] + bia1;
            }
            if (m0 + 8 < MTOT) {
                g_xp[(size_t)(m0 + 8) * NGATE + n0]     = acc[mt][nt][2] + bia0;
                g_xp[(size_t)(m0 + 8) * NGATE + n0 + 1] = acc[mt][nt][3] + bia1;
            }
        }
    }
}

// ---------------- persistent recurrent kernel --------------------------------
// 128 CTAs x 256 threads. CTA c owns hidden units [c*8, c*8+8) (32 W_hh rows).
// W_hh tf32 fragments live in REGISTERS (128 regs/thread). Per step:
//   read h broadcast (pre-packed tf32 frags, 2x LDG.128.cg per k-slice),
//   8-way K-split mma, reduce in SMEM, gate math, store packed h, grid barrier.
__global__ void __launch_bounds__(256, 1)
lstm_kernel(const float* __restrict__ h0, const float* __restrict__ c0,
            const float* __restrict__ W_hh, float* __restrict__ out, int out_size)
{
    __shared__ float red[8448];   // idx(m,n,w) = (m*33+n)*8+w

    const int tid = threadIdx.x, lane = tid & 31, wid = tid >> 5;
    const int g = lane >> 2, tg = lane & 3;
    const int j0 = blockIdx.x * 8;

    // ---- prologue: pack h0 into fragment layout (one element per thread) ----
    {
        int i = blockIdx.x * 256 + tid;     // 0..32767 == BATCH*HID
        int b = i >> 10, j = i & 1023;
        g_hp[0][hp_index(b, j)] = f2tf(h0[i]);
    }

    // ---- load this CTA's W_hh fragments into registers (tf32) ----
    unsigned bw[16][4][2];
#pragma unroll
    for (int s = 0; s < 16; ++s) {
#pragma unroll
        for (int nt = 0; nt < 4; ++nt) {
            int r = nt * 8 + g;                 // local gate-row 0..31
            int q = r >> 3, jr = r & 7;
            const float* wrow = W_hh + (size_t)(q * 1024 + j0 + jr) * 1024
                                     + wid * 128 + s * 8 + tg;
            bw[s][nt][0] = f2tf(wrow[0]);
            bw[s][nt][1] = f2tf(wrow[4]);
        }
    }

    const int b = tid >> 3, jj = tid & 7;   // this thread's LSTM cell (b, j0+jj)
    float c_reg = c0[b * 1024 + j0 + jj];
    const int hp_idx = hp_index(b, j0 + jj);           // packed slot for our h
    float* out_cell = out + ((size_t)b * TSTEPS) * 1024 + j0 + jj;

    grid_bar(tid);   // h0 pack visible chip-wide

    for (int t = 0; t < TSTEPS; ++t) {
        const unsigned* hb = g_hp[t & 1];

        // prefetch gate pre-activations (DRAM, consumed after mma phase)
        float xpv[4];
        const float* xprow = &g_xp[(size_t)(t * 32 + b) * NGATE + j0 + jj];
#pragma unroll
        for (int q = 0; q < 4; ++q) xpv[q] = __ldg(xprow + q * 1024);

        // mma phase: warp wid owns K slice [wid*128, wid*128+128)
        float C[8][4];
#pragma unroll
        for (int i = 0; i < 8; ++i) { C[i][0] = 0.f; C[i][1] = 0.f; C[i][2] = 0.f; C[i][3] = 0.f; }

#pragma unroll
        for (int s = 0; s < 16; ++s) {
            const unsigned* p = hb + ((wid * 16 + s) * 32 + lane) * 8;
            uint4 A0 = ldcg4(p);        // batches 0..15  (a0..a3)
            uint4 A1 = ldcg4(p + 4);    // batches 16..31 (a4..a7)
#pragma unroll
            for (int nt = 0; nt < 4; ++nt) {
                mma8(C[nt],     A0.x, A0.y, A0.z, A0.w, bw[s][nt][0], bw[s][nt][1]);
                mma8(C[4 + nt], A1.x, A1.y, A1.z, A1.w, bw[s][nt][0], bw[s][nt][1]);
            }
        }

        // K-split partials -> SMEM
#pragma unroll
        for (int mt = 0; mt < 2; ++mt) {
#pragma unroll
            for (int nt = 0; nt < 4; ++nt) {
                float* cc = C[mt * 4 + nt];
                int m  = mt * 16 + g;
                int n0 = nt * 8 + tg * 2;
                red[((m)     * 33 + n0    ) * 8 + wid] = cc[0];
                red[((m)     * 33 + n0 + 1) * 8 + wid] = cc[1];
                red[((m + 8) * 33 + n0    ) * 8 + wid] = cc[2];
                red[((m + 8) * 33 + n0 + 1) * 8 + wid] = cc[3];
            }
        }
        __syncthreads();

        // gate math: one thread per (b, jj)
        float z[4];
#pragma unroll
        for (int q = 0; q < 4; ++q) {
            int r = q * 8 + jj;
            const float4* p = (const float4*)&red[(b * 33 + r) * 8];
            float4 s0 = p[0], s1 = p[1];
            z[q] = xpv[q] + (((s0.x + s0.y) + (s0.z + s0.w)) +
                             ((s1.x + s1.y) + (s1.z + s1.w)));
        }
        float iv = fsig(z[0]);
        float fv = fsig(z[1]);
        float gv = ftanh(z[2]);
        float ov = fsig(z[3]);
        c_reg = fv * c_reg + iv * gv;
        float hv = ov * ftanh(c_reg);

        g_hp[(t + 1) & 1][hp_idx] = f2tf(hv);      // publish packed h
        out_cell[(size_t)t * 1024] = hv;           // res[b][t][j]
        if (t == TSTEPS - 1 && out_size >= RES_ELEMS + 2 * BATCH * HID) {
            out[RES_ELEMS + b * 1024 + j0 + jj]               = hv;     // hT
            out[RES_ELEMS + BATCH * HID + b * 1024 + j0 + jj] = c_reg;  // cT
        }

        if (t < TSTEPS - 1) grid_bar(tid);
        else __syncthreads();   // red reuse safety on last iter (no-op cost)
    }
}

// ---------------- launch ------------------------------------------------------
extern "C" void kernel_launch(void* const* d_in, const int* in_sizes, int n_in,
                              void* d_out, int out_size)
{
    const int*   tgt  = (const int*)  d_in[0];
    const float* h0   = (const float*)d_in[1];
    const float* c0   = (const float*)d_in[2];
    // d_in[3] encoder_outputs, d_in[4] src_lengths: unused by the reference
    const float* emb  = (const float*)d_in[5];
    const float* W_ih = (const float*)d_in[6];
    const float* W_hh = (const float*)d_in[7];
    const float* b_ih = (const float*)d_in[8];
    const float* b_hh = (const float*)d_in[9];
    float* out = (float*)d_out;

    dim3 grid_x(32, 128);                 // (n blocks, m blocks)
    xproj_kernel<<<grid_x, 256>>>(tgt, emb, W_ih, b_ih, b_hh);

    lstm_kernel<<<128, 256>>>(h0, c0, W_hh, out, out_size);
}